// round 5
// baseline (speedup 1.0000x reference)
#include <cuda_runtime.h>
#include <math.h>
#include <stdint.h>

#define BATCH 64
#define H 64
#define W 96
#define HW (H * W)
#define UV 81
#define NCH 16

#define TILE 64
#define BY 3
#define NTHREADS (TILE * BY)
#define NCHUNK (UV * TILE / 4)     // 1296 float4 chunks per tile

// ln2/ln49, ln2/ln81
#define K_LOC 0.17811242f
#define K_GLB 0.15774409f
#define L2E   1.4426950408889634f

// ---- packed f32x2 helpers ----
__device__ __forceinline__ uint64_t pk2(float a, float b) {
    uint64_t r;
    asm("mov.b64 %0, {%1, %2};" : "=l"(r) : "f"(a), "f"(b));
    return r;
}
__device__ __forceinline__ float hadd2(uint64_t p) {
    uint32_t lo, hi;
    asm("mov.b64 {%0, %1}, %2;" : "=r"(lo), "=r"(hi) : "l"(p));
    return __uint_as_float(lo) + __uint_as_float(hi);
}
#define FMA2(d, a, b, c) asm("fma.rn.f32x2 %0, %1, %2, %3;" : "=l"(d) : "l"(a), "l"(b), "l"(c))
#define MUL2(d, a, b)    asm("mul.rn.f32x2 %0, %1, %2;"     : "=l"(d) : "l"(a), "l"(b))
#define ADD2(d, a, b)    asm("add.rn.f32x2 %0, %1, %2;"     : "=l"(d) : "l"(a), "l"(b))

__device__ __forceinline__ float ex2(float x) {
    float r;
    asm("ex2.approx.f32 %0, %1;" : "=f"(r) : "f"(x));
    return r;
}
__device__ __forceinline__ float lg2(float x) {
    float r;
    asm("lg2.approx.f32 %0, %1;" : "=f"(r) : "f"(x));
    return r;
}

__global__ __launch_bounds__(NTHREADS) void segnet_flowreg_warp_kernel(
    const float* __restrict__ cost,
    const float* __restrict__ feat,
    float* __restrict__ out)
{
    __shared__ __align__(16) float buf[UV][TILE];   // 20.25 KB cost tile
    __shared__ float s_max[BY][TILE];
    __shared__ int   s_am [BY][TILE];
    __shared__ float s_part[6][BY][TILE];

    const int tx  = threadIdx.x;
    const int ty  = threadIdx.y;
    const int tid = tx + TILE * ty;

    const int tile = blockIdx.x;
    const int b    = tile / (HW / TILE);
    const int hw0  = (tile % (HW / TILE)) * TILE;
    const int hw   = hw0 + tx;
    const int h    = hw / W;
    const int w    = hw - h * W;

    // ---- stage cost tile: float4 LDG -> float4 STS (both fully coalesced) ----
    {
        const float4* g4 = (const float4*)(cost + (size_t)b * UV * HW + hw0);
        for (int q = tid; q < NCHUNK; q += NTHREADS) {
            int uv = q >> 4, p4 = q & 15;
            float4 v = __ldg(g4 + (size_t)uv * (HW / 4) + p4);
            ((float4*)buf[uv])[p4] = v;
        }
    }
    __syncthreads();

    // ---- pass 1: per-chunk max/argmax ----
    float m  = -INFINITY;
    int   am = ty * 27;
#pragma unroll
    for (int j = 0; j < 27; j++) {
        float v = buf[ty * 27 + j][tx];
        if (v > m) { m = v; am = ty * 27 + j; }   // strict > : first occurrence
    }
    s_max[ty][tx] = m;
    s_am [ty][tx] = am;
    __syncthreads();

    float gm  = s_max[0][tx];
    int   gam = s_am [0][tx];
#pragma unroll
    for (int q = 1; q < BY; q++) {
        float v = s_max[q][tx];
        if (v > gm) { gm = v; gam = s_am[q][tx]; }
    }
    const int u0 = gam / 9;
    const int v0 = gam - 9 * u0;

    // ---- v-window masks (packed pairs) ----
    float mv[9];
#pragma unroll
    for (int v = 0; v < 9; v++)
        mv[v] = ((unsigned)(v - v0 + 3) <= 6u) ? 1.0f : 0.0f;
    uint64_t mv2[4];
#pragma unroll
    for (int p = 0; p < 4; p++) mv2[p] = pk2(mv[2 * p], mv[2 * p + 1]);
    const float mv8 = mv[8];

    uint64_t dv2[4];
    dv2[0] = pk2(-4.f, -3.f); dv2[1] = pk2(-2.f, -1.f);
    dv2[2] = pk2( 0.f,  1.f); dv2[3] = pk2( 2.f,  3.f);

    const float ngm = -gm * L2E;      // d' = c*log2e - gm*log2e ; e = 2^d'

    // ---- pass 2: packed exp sums; window max == global max (argmax in-window) ----
    uint64_t Sg2  = pk2(0.f, 0.f), Sg12 = Sg2, Sw2 = Sg2, Sw12 = Sg2, Sy2 = Sg2, Sx2 = Sg2;
    float Sg_s = 0.f, Sg1_s = 0.f, Sw_s = 0.f, Sw1_s = 0.f, Sy_s = 0.f, Sx_s = 0.f;

#pragma unroll
    for (int ul = 0; ul < 3; ul++) {
        const int   u  = ty * 3 + ul;
        const float uf = ((unsigned)(u - u0 + 3) <= 6u) ? 1.0f : 0.0f;
        const float du = (float)(u - 4);
        const uint64_t uf2 = pk2(uf, uf);
        const uint64_t s2  = pk2(uf * du, uf * du);

        uint64_t Rw2 = pk2(0.f, 0.f), Rw12 = Rw2, Ry2 = Rw2;  // row accumulators
#pragma unroll
        for (int p = 0; p < 4; p++) {
            float c0 = buf[u * 9 + 2 * p][tx];
            float c1 = buf[u * 9 + 2 * p + 1][tx];
            float d0 = fmaf(c0, L2E, ngm);
            float d1 = fmaf(c1, L2E, ngm);
            float e0 = ex2(d0), e1 = ex2(d1);
            uint64_t e2 = pk2(e0, e1), d2 = pk2(d0, d1);
            ADD2(Sg2, Sg2, e2);
            FMA2(Sg12, e2, d2, Sg12);
            uint64_t ew2;
            MUL2(ew2, e2, mv2[p]);
            ADD2(Rw2, Rw2, ew2);
            FMA2(Rw12, ew2, d2, Rw12);
            FMA2(Ry2, ew2, dv2[p], Ry2);
        }
        // leftover v = 8 (dv = +4)
        float c8 = buf[u * 9 + 8][tx];
        float d8 = fmaf(c8, L2E, ngm);
        float e8 = ex2(d8);
        Sg_s += e8;
        Sg1_s = fmaf(e8, d8, Sg1_s);
        float ew8 = e8 * (uf * mv8);
        Sw_s += ew8;
        Sw1_s = fmaf(ew8, d8, Sw1_s);
        Sy_s  = fmaf(ew8, 4.f, Sy_s);
        Sx_s  = fmaf(ew8, du, Sx_s);
        // fold row into thread accumulators, gated by u-window
        FMA2(Sw2,  uf2, Rw2,  Sw2);
        FMA2(Sw12, uf2, Rw12, Sw12);
        FMA2(Sy2,  uf2, Ry2,  Sy2);
        FMA2(Sx2,  s2,  Rw2,  Sx2);
    }

    // horizontal reduce (d'-units for entropy terms; rescaled by ln2 via K_*)
    s_part[0][ty][tx] = hadd2(Sw2)  + Sw_s;
    s_part[1][ty][tx] = hadd2(Sx2)  + Sx_s;
    s_part[2][ty][tx] = hadd2(Sy2)  + Sy_s;
    s_part[3][ty][tx] = hadd2(Sg2)  + Sg_s;
    s_part[4][ty][tx] = hadd2(Sg12) + Sg1_s;
    s_part[5][ty][tx] = hadd2(Sw12) + Sw1_s;
    __syncthreads();

    // all threads combine Sw, Sx, Sy (need fx, fy locally; sync-free)
    float Sw = 0.f, Sx = 0.f, Sy = 0.f;
#pragma unroll
    for (int q = 0; q < BY; q++) {
        Sw += s_part[0][q][tx];
        Sx += s_part[1][q][tx];
        Sy += s_part[2][q][tx];
    }
    const float invSw = 1.0f / Sw;
    const float fx = Sx * invSw;    // flow x = E[u-4]
    const float fy = Sy * invSw;    // flow y = E[v-4]

    float* flow_o = out;
    float* ent_o  = out + (size_t)BATCH * 2 * HW;
    float* warp_o = out + (size_t)BATCH * 4 * HW;

    if (ty == 0) {
        float Sg = 0.f, Sg1p = 0.f, Sw1p = 0.f;
#pragma unroll
        for (int q = 0; q < BY; q++) {
            Sg   += s_part[3][q][tx];
            Sg1p += s_part[4][q][tx];
            Sw1p += s_part[5][q][tx];
        }
        const float lent = (lg2(Sw) - Sw1p * invSw) * K_LOC;
        const float gent = (lg2(Sg) - Sg1p / Sg)    * K_GLB;
        flow_o[((size_t)b * 2 + 0) * HW + hw] = fx;
        flow_o[((size_t)b * 2 + 1) * HW + hw] = fy;
        ent_o [((size_t)b * 2 + 0) * HW + hw] = lent;
        ent_o [((size_t)b * 2 + 1) * HW + hw] = gent;
    }

    // ---- bilinear backward warp (align_corners=True, zero pad); channels over ty ----
    const float px = (float)w + fx;
    const float py = (float)h + fy;
    const float x0f = floorf(px), y0f = floorf(py);
    const float wx = px - x0f,   wy = py - y0f;
    const int x0 = (int)x0f, y0 = (int)y0f;
    const int x1 = x0 + 1,   y1 = y0 + 1;
    const bool vx0 = (x0 >= 0) & (x0 < W);
    const bool vx1 = (x1 >= 0) & (x1 < W);
    const bool vy0 = (y0 >= 0) & (y0 < H);
    const bool vy1 = (y1 >= 0) & (y1 < H);

    float w00 = (1.f - wx) * (1.f - wy) * ((vx0 & vy0) ? 1.f : 0.f);
    float w01 = wx         * (1.f - wy) * ((vx1 & vy0) ? 1.f : 0.f);
    float w10 = (1.f - wx) * wy         * ((vx0 & vy1) ? 1.f : 0.f);
    float w11 = wx         * wy         * ((vx1 & vy1) ? 1.f : 0.f);

    const float nx = 2.f * px / (float)(W - 1) - 1.f;
    const float ny = 2.f * py / (float)(H - 1) - 1.f;
    const float msk = (fabsf(nx) < 1.f && fabsf(ny) < 1.f) ? 1.f : 0.f;
    w00 *= msk; w01 *= msk; w10 *= msk; w11 *= msk;

    const int x0c = min(max(x0, 0), W - 1), x1c = min(max(x1, 0), W - 1);
    const int y0c = min(max(y0, 0), H - 1), y1c = min(max(y1, 0), H - 1);
    const int o00 = y0c * W + x0c, o01 = y0c * W + x1c;
    const int o10 = y1c * W + x0c, o11 = y1c * W + x1c;

    const float* fb = feat + (size_t)b * NCH * HW;
#pragma unroll
    for (int ch = ty; ch < NCH; ch += BY) {
        const float* f = fb + ch * HW;
        float val = w00 * __ldg(f + o00) + w01 * __ldg(f + o01)
                  + w10 * __ldg(f + o10) + w11 * __ldg(f + o11);
        warp_o[((size_t)b * NCH + ch) * HW + hw] = val;
    }
}

extern "C" void kernel_launch(void* const* d_in, const int* in_sizes, int n_in,
                              void* d_out, int out_size) {
    const float* cost = (const float*)d_in[0];
    const float* feat = (const float*)d_in[1];
    float* out = (float*)d_out;

    dim3 block(TILE, BY);                    // 192 threads
    int blocks = BATCH * HW / TILE;          // 6144
    segnet_flowreg_warp_kernel<<<blocks, block>>>(cost, feat, out);
}

// round 6
// speedup vs baseline: 1.3326x; 1.3326x over previous
#include <cuda_runtime.h>
#include <math.h>
#include <stdint.h>

#define BATCH 64
#define H 64
#define W 96
#define HW (H * W)
#define UV 81
#define NCH 16

#define BX 32        // pixels per block (1 warp per u-row)
#define BY 9         // one thread-row per u
#define NTHREADS (BX * BY)   // 288

#define L2E       1.4426950408889634f
#define LN2_LN49  0.17811242f
#define INV_LN49  0.25694882f
#define LN2_LN81  0.15774409f
#define INV_LN81  0.22756237f

__device__ __forceinline__ float ex2(float x) {
    float r; asm("ex2.approx.f32 %0, %1;" : "=f"(r) : "f"(x)); return r;
}
__device__ __forceinline__ float lg2(float x) {
    float r; asm("lg2.approx.f32 %0, %1;" : "=f"(r) : "f"(x)); return r;
}

__global__ __launch_bounds__(NTHREADS) void segnet_flowreg_warp_kernel(
    const float* __restrict__ cost,
    const float* __restrict__ feat,
    float* __restrict__ out)
{
    __shared__ float s_max[BY][BX];
    __shared__ int   s_am [BY][BX];
    __shared__ float s_part[5][BY][BX];   // Sw, Sy, Sg, Sgc, Swc

    const int tx  = threadIdx.x;          // pixel lane
    const int ty  = threadIdx.y;          // u row (0..8)

    const int pix = blockIdx.x * BX + tx;
    const int b   = pix / HW;
    const int hw  = pix - b * HW;
    const int h   = hw / W;
    const int w   = hw - h * W;

    // ---- pass 1: load 9 values (this u-row), exp WITHOUT max-subtraction,
    //      global sums + row max/argmax, all fused (exp overlaps loads) ----
    const float* cp = cost + ((size_t)b * UV + ty * 9) * HW + hw;
    float c[9], e[9];
    float m = -INFINITY;
    int   amv = 0;
    float Sg = 0.f, Sgc = 0.f;
#pragma unroll
    for (int v = 0; v < 9; v++) {
        float cv = __ldcs(cp + (size_t)v * HW);
        c[v] = cv;
        if (cv > m) { m = cv; amv = v; }          // strict > : first occurrence
        float ev = ex2(cv * L2E);                 // e^{c}
        e[v] = ev;
        Sg  += ev;
        Sgc  = fmaf(ev, cv, Sgc);
    }
    s_max[ty][tx] = m;
    s_am [ty][tx] = ty * 9 + amv;
    __syncthreads();

    // ---- global argmax (ascending q preserves first-occurrence tie-break) ----
    float gm  = s_max[0][tx];
    int   gam = s_am [0][tx];
#pragma unroll
    for (int q = 1; q < BY; q++) {
        float v = s_max[q][tx];
        if (v > gm) { gam = s_am[q][tx]; gm = v; }
    }
    const int u0 = gam / 9;
    const int v0 = gam - 9 * u0;

    // ---- pass 2: window sums from registers (u-gate warp-uniform) ----
    float Sw = 0.f, Swc = 0.f, Sy = 0.f;
    if ((unsigned)(ty - u0 + 3) <= 6u) {          // uniform across the warp
#pragma unroll
        for (int v = 0; v < 9; v++) {
            float mv = ((unsigned)(v - v0 + 3) <= 6u) ? 1.0f : 0.0f;
            float ew = e[v] * mv;
            Sw += ew;
            Swc = fmaf(ew, c[v], Swc);
            Sy  = fmaf(ew, (float)(v - 4), Sy);
        }
    }
    s_part[0][ty][tx] = Sw;
    s_part[1][ty][tx] = Sy;
    s_part[2][ty][tx] = Sg;
    s_part[3][ty][tx] = Sgc;
    s_part[4][ty][tx] = Swc;
    __syncthreads();

    // ---- combine (all threads need fx,fy; Sx = sum du_q * Sw_q) ----
    float SwT = 0.f, SxT = 0.f, SyT = 0.f;
#pragma unroll
    for (int q = 0; q < BY; q++) {
        float swq = s_part[0][q][tx];
        SwT += swq;
        SxT  = fmaf((float)(q - 4), swq, SxT);
        SyT += s_part[1][q][tx];
    }
    const float invSw = 1.0f / SwT;
    const float fx = SxT * invSw;                 // flow x = E[u-4]
    const float fy = SyT * invSw;                 // flow y = E[v-4]

    float* flow_o = out;
    float* ent_o  = out + (size_t)BATCH * 2 * HW;
    float* warp_o = out + (size_t)BATCH * 4 * HW;

    if (ty == 0) {
        float SgT = 0.f, SgcT = 0.f, SwcT = 0.f;
#pragma unroll
        for (int q = 0; q < BY; q++) {
            SgT  += s_part[2][q][tx];
            SgcT += s_part[3][q][tx];
            SwcT += s_part[4][q][tx];
        }
        // -sum p ln p = ln S - (sum e*c)/S   (p = e^c / S)
        const float lent = lg2(SwT) * LN2_LN49 - (SwcT * invSw) * INV_LN49;
        const float gent = lg2(SgT) * LN2_LN81 - (SgcT / SgT)   * INV_LN81;
        flow_o[((size_t)b * 2 + 0) * HW + hw] = fx;
        flow_o[((size_t)b * 2 + 1) * HW + hw] = fy;
        ent_o [((size_t)b * 2 + 0) * HW + hw] = lent;
        ent_o [((size_t)b * 2 + 1) * HW + hw] = gent;
    }

    // ---- bilinear backward warp (align_corners=True, zero pad); channels over ty ----
    const float px = (float)w + fx;
    const float py = (float)h + fy;
    const float x0f = floorf(px), y0f = floorf(py);
    const float wx = px - x0f,   wy = py - y0f;
    const int x0 = (int)x0f, y0 = (int)y0f;
    const int x1 = x0 + 1,   y1 = y0 + 1;
    const bool vx0 = (x0 >= 0) & (x0 < W);
    const bool vx1 = (x1 >= 0) & (x1 < W);
    const bool vy0 = (y0 >= 0) & (y0 < H);
    const bool vy1 = (y1 >= 0) & (y1 < H);

    float w00 = (1.f - wx) * (1.f - wy) * ((vx0 & vy0) ? 1.f : 0.f);
    float w01 = wx         * (1.f - wy) * ((vx1 & vy0) ? 1.f : 0.f);
    float w10 = (1.f - wx) * wy         * ((vx0 & vy1) ? 1.f : 0.f);
    float w11 = wx         * wy         * ((vx1 & vy1) ? 1.f : 0.f);

    const float nx = 2.f * px / (float)(W - 1) - 1.f;
    const float ny = 2.f * py / (float)(H - 1) - 1.f;
    const float msk = (fabsf(nx) < 1.f && fabsf(ny) < 1.f) ? 1.f : 0.f;
    w00 *= msk; w01 *= msk; w10 *= msk; w11 *= msk;

    const int x0c = min(max(x0, 0), W - 1), x1c = min(max(x1, 0), W - 1);
    const int y0c = min(max(y0, 0), H - 1), y1c = min(max(y1, 0), H - 1);
    const int o00 = y0c * W + x0c, o01 = y0c * W + x1c;
    const int o10 = y1c * W + x0c, o11 = y1c * W + x1c;

    const float* fb = feat + (size_t)b * NCH * HW;
#pragma unroll
    for (int ch = ty; ch < NCH; ch += BY) {
        const float* f = fb + ch * HW;
        float val = w00 * __ldg(f + o00) + w01 * __ldg(f + o01)
                  + w10 * __ldg(f + o10) + w11 * __ldg(f + o11);
        __stcs(&warp_o[((size_t)b * NCH + ch) * HW + hw], val);
    }
}

extern "C" void kernel_launch(void* const* d_in, const int* in_sizes, int n_in,
                              void* d_out, int out_size) {
    const float* cost = (const float*)d_in[0];
    const float* feat = (const float*)d_in[1];
    float* out = (float*)d_out;

    dim3 block(BX, BY);                     // 288 threads
    int blocks = BATCH * HW / BX;           // 12288
    segnet_flowreg_warp_kernel<<<blocks, block>>>(cost, feat, out);
}

// round 8
// speedup vs baseline: 1.6257x; 1.2200x over previous
#include <cuda_runtime.h>
#include <math.h>
#include <stdint.h>

#define BATCH 64
#define H 64
#define W 96
#define HW (H * W)
#define UV 81
#define NCH 16

#define BX 64
#define BY 3
#define NTHREADS (BX * BY)

#define L2E       1.4426950408889634f
#define LN2_LN49  0.17811242f
#define LN2_LN81  0.15774409f

__device__ __forceinline__ float ex2(float x) {
    float r; asm("ex2.approx.f32 %0, %1;" : "=f"(r) : "f"(x)); return r;
}
__device__ __forceinline__ float lg2(float x) {
    float r; asm("lg2.approx.f32 %0, %1;" : "=f"(r) : "f"(x)); return r;
}

__global__ __launch_bounds__(NTHREADS, 7) void segnet_flowreg_warp_kernel(
    const float* __restrict__ cost,
    const float* __restrict__ feat,
    float* __restrict__ out)
{
    __shared__ float s_max[BY][BX];
    __shared__ int   s_am [BY][BX];
    __shared__ float s_part[6][BY][BX];   // Sw, Sx, Sy, Sg, Sgt, Swt

    const int tx  = threadIdx.x;
    const int ty  = threadIdx.y;

    const int pix = blockIdx.x * BX + tx;
    const int b   = pix / HW;
    const int hw  = pix - b * HW;
    const int h   = hw / W;
    const int w   = hw - h * W;

    // ---- pass 1 (fused): load 27 slices, t = c*log2e, e = 2^t,
    //      global sums + chunk max. exp/sum work overlaps load latency. ----
    const float* cp = cost + ((size_t)b * UV + ty * 27) * HW + hw;
    float t[27];
    float m = -INFINITY;
    float Sg = 0.f, Sgt = 0.f;            // sum e, sum e*t  (t-units = log2 domain)
#pragma unroll
    for (int j = 0; j < 27; j++) {
        float tv = __ldcs(cp + (size_t)j * HW) * L2E;
        t[j] = tv;
        m = fmaxf(m, tv);
        float ev = ex2(tv);
        Sg += ev;
        Sgt = fmaf(ev, tv, Sgt);
    }
    s_max[ty][tx] = m;
    __syncthreads();

    // ---- global max, then first-occurrence argmax scan ----
    float gm = fmaxf(fmaxf(s_max[0][tx], s_max[1][tx]), s_max[2][tx]);
    int am = 1 << 30;
#pragma unroll
    for (int j = 26; j >= 0; j--)          // descending: last write wins = smallest j
        if (t[j] == gm) am = ty * 27 + j;
    s_am[ty][tx] = am;
    __syncthreads();
    int gam = min(min(s_am[0][tx], s_am[1][tx]), s_am[2][tx]);
    const int u0 = gam / 9;
    const int v0 = gam - 9 * u0;

    // ---- v-window masks (9 values, reused across 3 rows) ----
    float mv[9];
#pragma unroll
    for (int v = 0; v < 9; v++)
        mv[v] = ((unsigned)(v - v0 + 3) <= 6u) ? 1.0f : 0.0f;

    // ---- pass 2: windowed sums, exp recomputed (MUFU is cheap) ----
    float Sw = 0.f, Swt = 0.f, Sx = 0.f, Sy = 0.f;
#pragma unroll
    for (int ul = 0; ul < 3; ul++) {
        const int   u  = ty * 3 + ul;
        const float uf = ((unsigned)(u - u0 + 3) <= 6u) ? 1.0f : 0.0f;
        const float du = (float)(u - 4);
        float Rw = 0.f, Rwt = 0.f, Ry = 0.f;
#pragma unroll
        for (int v = 0; v < 9; v++) {
            float tv = t[ul * 9 + v];
            float ew = ex2(tv) * mv[v];
            Rw += ew;
            Rwt = fmaf(ew, tv, Rwt);
            Ry  = fmaf(ew, (float)(v - 4), Ry);
        }
        Sw  = fmaf(uf, Rw,  Sw);
        Swt = fmaf(uf, Rwt, Swt);
        Sy  = fmaf(uf, Ry,  Sy);
        Sx  = fmaf(uf * du, Rw, Sx);
    }
    s_part[0][ty][tx] = Sw;   s_part[1][ty][tx] = Sx;
    s_part[2][ty][tx] = Sy;   s_part[3][ty][tx] = Sg;
    s_part[4][ty][tx] = Sgt;  s_part[5][ty][tx] = Swt;
    __syncthreads();

    // ---- combine (redundant per ty; sync-free) ----
    float SwT = 0.f, SxT = 0.f, SyT = 0.f;
#pragma unroll
    for (int q = 0; q < BY; q++) {
        SwT += s_part[0][q][tx];
        SxT += s_part[1][q][tx];
        SyT += s_part[2][q][tx];
    }
    const float invSw = 1.0f / SwT;
    const float fx = SxT * invSw;          // flow x = E[u-4]
    const float fy = SyT * invSw;          // flow y = E[v-4]

    float* flow_o = out;
    float* ent_o  = out + (size_t)BATCH * 2 * HW;
    float* warp_o = out + (size_t)BATCH * 4 * HW;

    if (ty == 0) {
        float SgT = 0.f, SgtT = 0.f, SwtT = 0.f;
#pragma unroll
        for (int q = 0; q < BY; q++) {
            SgT  += s_part[3][q][tx];
            SgtT += s_part[4][q][tx];
            SwtT += s_part[5][q][tx];
        }
        // -sum p ln p = ln2 * (lg2 S - (sum e*t)/S)
        const float lent = (lg2(SwT) - SwtT * invSw) * LN2_LN49;
        const float gent = (lg2(SgT) - SgtT / SgT)   * LN2_LN81;
        flow_o[((size_t)b * 2 + 0) * HW + hw] = fx;
        flow_o[((size_t)b * 2 + 1) * HW + hw] = fy;
        ent_o [((size_t)b * 2 + 0) * HW + hw] = lent;
        ent_o [((size_t)b * 2 + 1) * HW + hw] = gent;
    }

    // ---- bilinear backward warp (align_corners=True, zero pad); channels over ty ----
    const float px = (float)w + fx;
    const float py = (float)h + fy;
    const float x0f = floorf(px), y0f = floorf(py);
    const float wx = px - x0f,   wy = py - y0f;
    const int x0 = (int)x0f, y0 = (int)y0f;
    const int x1 = x0 + 1,   y1 = y0 + 1;
    const bool vx0 = (x0 >= 0) & (x0 < W);
    const bool vx1 = (x1 >= 0) & (x1 < W);
    const bool vy0 = (y0 >= 0) & (y0 < H);
    const bool vy1 = (y1 >= 0) & (y1 < H);

    float w00 = (1.f - wx) * (1.f - wy) * ((vx0 & vy0) ? 1.f : 0.f);
    float w01 = wx         * (1.f - wy) * ((vx1 & vy0) ? 1.f : 0.f);
    float w10 = (1.f - wx) * wy         * ((vx0 & vy1) ? 1.f : 0.f);
    float w11 = wx         * wy         * ((vx1 & vy1) ? 1.f : 0.f);

    const float nx = 2.f * px / (float)(W - 1) - 1.f;
    const float ny = 2.f * py / (float)(H - 1) - 1.f;
    const float msk = (fabsf(nx) < 1.f && fabsf(ny) < 1.f) ? 1.f : 0.f;
    w00 *= msk; w01 *= msk; w10 *= msk; w11 *= msk;

    const int x0c = min(max(x0, 0), W - 1), x1c = min(max(x1, 0), W - 1);
    const int y0c = min(max(y0, 0), H - 1), y1c = min(max(y1, 0), H - 1);
    const int o00 = y0c * W + x0c, o01 = y0c * W + x1c;
    const int o10 = y1c * W + x0c, o11 = y1c * W + x1c;

    const float* fb = feat + (size_t)b * NCH * HW;
#pragma unroll
    for (int ch = ty; ch < NCH; ch += BY) {
        const float* f = fb + ch * HW;
        float val = w00 * __ldg(f + o00) + w01 * __ldg(f + o01)
                  + w10 * __ldg(f + o10) + w11 * __ldg(f + o11);
        __stcs(&warp_o[((size_t)b * NCH + ch) * HW + hw], val);
    }
}

extern "C" void kernel_launch(void* const* d_in, const int* in_sizes, int n_in,
                              void* d_out, int out_size) {
    const float* cost = (const float*)d_in[0];
    const float* feat = (const float*)d_in[1];
    float* out = (float*)d_out;

    dim3 block(BX, BY);                    // 192 threads
    int blocks = BATCH * HW / BX;          // 6144
    segnet_flowreg_warp_kernel<<<blocks, block>>>(cost, feat, out);
}